// round 5
// baseline (speedup 1.0000x reference)
#include <cuda_runtime.h>
#include <cuda_bf16.h>
#include <cstdint>

#define NB 512      // batch
#define NT 256      // time steps
#define NF 128      // features
#define NH 1024     // hidden
#define NZ 4096     // 4*H
#define KTOT 1152   // NF + NH
#define FEATP 2064  // padded feature length
#define FEATR 2050  // real feature length

// ------------------ device scratch (no allocation allowed) ------------------
__device__ __nv_bfloat16 g_Wth[(size_t)NZ * KTOT];  // permuted W^T hi  [4096][1152]
__device__ __nv_bfloat16 g_Wtl[(size_t)NZ * KTOT];  // permuted W^T lo
__device__ __nv_bfloat16 g_xh[(size_t)NB * NT * NF];  // history hi
__device__ __nv_bfloat16 g_xl[(size_t)NB * NT * NF];  // history lo
__device__ __nv_bfloat16 g_hh[NB * NH];             // h hi (bf16)  [m][u]
__device__ __nv_bfloat16 g_hl[NB * NH];             // h lo (bf16)
__device__ float g_c[NB * NH];                      // c fp32 [m][u]
__device__ float g_hf[NB * NH];                     // h fp32 [m][u]
__device__ float g_feat[NB * FEATP];
__device__ float g_vlp[NB * 512];
__device__ float g_qlp[NB * 512];
__device__ float g_vle[NB * 512];
__device__ float g_qle[NB * 512];
__device__ float g_sq[NB];

// ------------------ helpers ------------------
__device__ __forceinline__ uint32_t smem_u32(const void* p)
{
    uint32_t a;
    asm("{ .reg .u64 t; cvta.to.shared.u64 t, %1; cvt.u32.u64 %0, t; }" : "=r"(a) : "l"(p));
    return a;
}

__device__ __forceinline__ void cpa16(uint32_t s, const void* g)
{
    asm volatile("cp.async.ca.shared.global [%0], [%1], 16;" :: "r"(s), "l"(g) : "memory");
}
#define CP_COMMIT() asm volatile("cp.async.commit_group;" ::: "memory")
#define CP_WAIT1()  asm volatile("cp.async.wait_group 1;" ::: "memory")

#define LDSM4(r0, r1, r2, r3, addr) \
    asm volatile("ldmatrix.sync.aligned.m8n8.x4.shared.b16 {%0,%1,%2,%3}, [%4];" \
                 : "=r"(r0), "=r"(r1), "=r"(r2), "=r"(r3) : "r"(addr))

#define MMA16816(d, a, b) \
    asm volatile("mma.sync.aligned.m16n8k16.row.col.f32.bf16.bf16.f32 " \
                 "{%0,%1,%2,%3}, {%4,%5,%6,%7}, {%8,%9}, {%0,%1,%2,%3};" \
                 : "+f"((d)[0]), "+f"((d)[1]), "+f"((d)[2]), "+f"((d)[3]) \
                 : "r"((a)[0]), "r"((a)[1]), "r"((a)[2]), "r"((a)[3]), \
                   "r"((b)[0]), "r"((b)[1]))

__device__ __forceinline__ uint32_t sw128(uint32_t off) { return off ^ ((off >> 3) & 0x70); }

__device__ __forceinline__ float fsig(float x)
{
    float e = __expf(-x);
    return __fdividef(1.f, 1.f + e);
}
__device__ __forceinline__ float ftanh(float x)
{
    float e = __expf(2.f * x);
    return 1.f - __fdividef(2.f, e + 1.f);
}

// ------------------ prep kernels ------------------
__global__ void k_init()
{
    int i = blockIdx.x * blockDim.x + threadIdx.x;
    if (i < NB * NH) {
        g_c[i] = 0.f;
        g_hh[i] = __float2bfloat16(0.f);
        g_hl[i] = __float2bfloat16(0.f);
    }
}

// Permuted, transposed, split weights: Wt[j][k] = W[k][ (j&3)*1024 + (j>>2) ]
__global__ void k_prep_w(const float* __restrict__ W)
{
    int id = blockIdx.x * blockDim.x + threadIdx.x;
    if (id >= NZ * KTOT) return;
    int j = id / KTOT;
    int k = id - j * KTOT;
    int u = j >> 2;
    int g = j & 3;
    float w = W[(size_t)k * NZ + g * NH + u];
    __nv_bfloat16 hi = __float2bfloat16(w);
    float lo = w - __bfloat162float(hi);
    g_Wth[id] = hi;
    g_Wtl[id] = __float2bfloat16(lo);
}

// Split history into bf16 hi/lo once (same [b][t][f] layout).
__global__ void k_prep_x(const float* __restrict__ hist)
{
    int id = blockIdx.x * blockDim.x + threadIdx.x;
    if (id >= NB * NT * NF) return;
    float v = hist[id];
    __nv_bfloat16 hi = __float2bfloat16(v);
    g_xh[id] = hi;
    g_xl[id] = __float2bfloat16(v - __bfloat162float(hi));
}

// ------------------ fused LSTM step: split-bf16 mma.sync GEMM + cell ------------------
// grid (32 n-tiles, 4 m-tiles), 512 threads (16 warps, 4x4 warp grid, warp=32m x 32n).
// CTA tile: 128 m x 128 cols; col c = u_local*4 + gate(i,j,f,o); K=1152 in 18 chunks of 64.
// smem stage: Ahi(16K) Alo(16K) Bhi(16K) Blo(16K) = 64KB; 3 stages = 192KB.
// Pipeline: ONE barrier per chunk; cp.async for c+2 issued after the barrier, overlapping
// compute of chunk c. Fragments double-buffered across k16 sub-iterations.
#define STAGE_BYTES 65536
#define SMEM_STEP_TOTAL (3 * STAGE_BYTES)

__global__ __launch_bounds__(512, 1) void k_step(const float* __restrict__ blstm, int t)
{
    extern __shared__ char smem[];
    const uint32_t sb = smem_u32(smem);
    const int tid = threadIdx.x;
    const int wid = tid >> 5;
    const int lane = tid & 31;
    const int ntile = blockIdx.x;
    const int mtile = blockIdx.y;
    const int m0 = mtile * 128;
    const int j0 = ntile * 128;
    const int u0 = ntile * 32;
    const int wm = wid & 3;    // 4 warp rows of 32 m
    const int wn = wid >> 2;   // 4 warp cols of 32 n

    float acc[2][4][4];
#pragma unroll
    for (int a = 0; a < 2; ++a)
#pragma unroll
        for (int b = 0; b < 4; ++b)
#pragma unroll
            for (int cc = 0; cc < 4; ++cc) acc[a][b][cc] = 0.f;

    // ---- chunk loader (cp.async), 512 threads -> 8 cp.async each ----
    auto load_chunk = [&](int c, uint32_t sbase) {
        const int kb = c * 64;
        const __nv_bfloat16 *aH, *aL;
        size_t astr;
        if (c < 2) {
            size_t base = ((size_t)m0 * NT + t) * NF + kb;
            aH = g_xh + base; aL = g_xl + base; astr = (size_t)NT * NF;
        } else {
            size_t base = (size_t)m0 * NH + (kb - NF);
            aH = g_hh + base; aL = g_hl + base; astr = NH;
        }
        const __nv_bfloat16* bH = g_Wth + (size_t)j0 * KTOT + kb;
        const __nv_bfloat16* bL = g_Wtl + (size_t)j0 * KTOT + kb;
#pragma unroll
        for (int s4 = 0; s4 < 2; ++s4) {
            int q = tid + s4 * 512;          // 0..1023
            int row = q >> 3;
            int seg = q & 7;
            uint32_t dsto = sw128((uint32_t)(row * 128 + seg * 16));
            cpa16(sbase + dsto,              aH + (size_t)row * astr + seg * 8);
            cpa16(sbase + 16384 + dsto,      aL + (size_t)row * astr + seg * 8);
            cpa16(sbase + 32768 + dsto,      bH + (size_t)row * KTOT + seg * 8);
            cpa16(sbase + 49152 + dsto,      bL + (size_t)row * KTOT + seg * 8);
        }
    };

    // ldmatrix lane addressing pieces
    const int lr = lane & 7;
    const int lg8 = (lane >> 3) & 1;
    const int lg16 = (lane >> 4) & 1;

    // fragment loader: all A/B hi+lo fragments for one k16 slice
    auto ld_frags = [&](uint32_t base, int k16,
                        uint32_t (&ah)[2][4], uint32_t (&al)[2][4],
                        uint32_t (&bh)[4][2], uint32_t (&bl)[4][2]) {
        const uint32_t aHb = base, aLb = base + 16384, bHb = base + 32768, bLb = base + 49152;
        const int kby = k16 * 32;
#pragma unroll
        for (int p = 0; p < 2; ++p) {
            uint32_t roff = (uint32_t)((wn * 32 + p * 16 + lg16 * 8 + lr) * 128
                                       + kby + lg8 * 16);
            uint32_t sw = sw128(roff);
            uint32_t r0, r1, r2, r3;
            LDSM4(r0, r1, r2, r3, bHb + sw);
            bh[p * 2][0] = r0; bh[p * 2][1] = r1; bh[p * 2 + 1][0] = r2; bh[p * 2 + 1][1] = r3;
            LDSM4(r0, r1, r2, r3, bLb + sw);
            bl[p * 2][0] = r0; bl[p * 2][1] = r1; bl[p * 2 + 1][0] = r2; bl[p * 2 + 1][1] = r3;
        }
#pragma unroll
        for (int mt = 0; mt < 2; ++mt) {
            uint32_t roff = (uint32_t)((wm * 32 + mt * 16 + lg8 * 8 + lr) * 128
                                       + kby + lg16 * 16);
            uint32_t sw = sw128(roff);
            LDSM4(ah[mt][0], ah[mt][1], ah[mt][2], ah[mt][3], aHb + sw);
            LDSM4(al[mt][0], al[mt][1], al[mt][2], al[mt][3], aLb + sw);
        }
    };

    load_chunk(0, sb);
    CP_COMMIT();
    load_chunk(1, sb + STAGE_BYTES);
    CP_COMMIT();

    uint32_t ahf[2][2][4], alf[2][2][4];
    uint32_t bhf[2][4][2], blf[2][4][2];

    int s_cur = 0;   // stage of chunk c
    int s_nxt = 2;   // stage for chunk c+2
    for (int c = 0; c < 18; ++c) {
        CP_WAIT1();          // chunk c's group complete (only c+1 may remain)
        __syncthreads();     // publish stage c; all warps done computing c-1

        // issue loads for c+2 (into stage previously used by chunk c-1) — overlaps compute c
        if (c + 2 < 18) load_chunk(c + 2, sb + (uint32_t)s_nxt * STAGE_BYTES);
        CP_COMMIT();

        const uint32_t base = sb + (uint32_t)s_cur * STAGE_BYTES;

        ld_frags(base, 0, ahf[0], alf[0], bhf[0], blf[0]);
#pragma unroll
        for (int k16 = 0; k16 < 4; ++k16) {
            const int cb = k16 & 1;
            if (k16 < 3)
                ld_frags(base, k16 + 1, ahf[cb ^ 1], alf[cb ^ 1], bhf[cb ^ 1], blf[cb ^ 1]);
            // term-major order: each acc's 3 updates separated by 7 independent MMAs
#pragma unroll
            for (int mt = 0; mt < 2; ++mt)
#pragma unroll
                for (int nt = 0; nt < 4; ++nt)
                    MMA16816(acc[mt][nt], ahf[cb][mt], bhf[cb][nt]);
#pragma unroll
            for (int mt = 0; mt < 2; ++mt)
#pragma unroll
                for (int nt = 0; nt < 4; ++nt)
                    MMA16816(acc[mt][nt], ahf[cb][mt], blf[cb][nt]);
#pragma unroll
            for (int mt = 0; mt < 2; ++mt)
#pragma unroll
                for (int nt = 0; nt < 4; ++nt)
                    MMA16816(acc[mt][nt], alf[cb][mt], bhf[cb][nt]);
        }

        s_cur = (s_cur == 2) ? 0 : s_cur + 1;
        s_nxt = (s_nxt == 2) ? 0 : s_nxt + 1;
    }

    // ---- fused cell epilogue (register accumulators) ----
    const int g = lane >> 2;
    const int tq = lane & 3;
    const bool even = (tq & 1) == 0;
#pragma unroll
    for (int mt = 0; mt < 2; ++mt) {
#pragma unroll
        for (int nt = 0; nt < 4; ++nt) {
            float c0 = acc[mt][nt][0], c1 = acc[mt][nt][1];
            float c2 = acc[mt][nt][2], c3 = acc[mt][nt][3];
            float s0 = even ? c2 : c0;
            float s1 = even ? c3 : c1;
            float r0 = __shfl_xor_sync(0xffffffffu, s0, 1);
            float r1 = __shfl_xor_sync(0xffffffffu, s1, 1);
            float zi, zj, zf, zo;
            int row;
            if (even) { row = g;     zi = c0; zj = c1; zf = r0; zo = r1; }
            else      { row = g + 8; zi = r0; zj = r1; zf = c2; zo = c3; }
            int u = u0 + wn * 8 + nt * 2 + (tq >> 1);
            int m = m0 + wm * 32 + mt * 16 + row;
            float bi = blstm[u];
            float bj = blstm[NH + u];
            float bf_ = blstm[2 * NH + u];
            float bo = blstm[3 * NH + u];
            size_t idx = (size_t)m * NH + u;
            float cold = g_c[idx];
            float cn = fsig(zf + bf_ + 1.f) * cold + fsig(zi + bi) * ftanh(zj + bj);
            float h = fsig(zo + bo) * ftanh(cn);
            g_c[idx] = cn;
            g_hf[idx] = h;
            __nv_bfloat16 hb = __float2bfloat16(h);
            g_hh[idx] = hb;
            g_hl[idx] = __float2bfloat16(h - __bfloat162float(hb));
        }
    }
}

// ------------------ feature assembly + head MLPs ------------------
__global__ void k_feat(const float* __restrict__ head)
{
    int idx = blockIdx.x * blockDim.x + threadIdx.x;
    if (idx >= NB * FEATP) return;
    int b = idx / FEATP;
    int k = idx - b * FEATP;
    float v;
    if (k < 2)            v = head[b * 3 + 1 + k];
    else if (k < 1026)    v = g_c[b * NH + (k - 2)];
    else if (k < 2050)    v = g_hf[b * NH + (k - 1026)];
    else                  v = 0.f;
    g_feat[idx] = v;
}

__global__ __launch_bounds__(256) void k_head_gemm(
    const float* __restrict__ W3, const float* __restrict__ b3,
    const float* __restrict__ W4, const float* __restrict__ b4,
    const float* __restrict__ W5, const float* __restrict__ b5,
    const float* __restrict__ W6, const float* __restrict__ b6)
{
    const int which = blockIdx.z;
    const float* Wm = (which == 0) ? W3 : (which == 1) ? W4 : (which == 2) ? W5 : W6;
    const float* bv = (which == 0) ? b3 : (which == 1) ? b4 : (which == 2) ? b5 : b6;
    float* Cout = (which == 0) ? g_vlp : (which == 1) ? g_qlp : (which == 2) ? g_vle : g_qle;

    __shared__ float As[16][64];
    __shared__ float Bs[16][64];
    const int tid = threadIdx.x;
    const int tx = tid & 15;
    const int ty = tid >> 4;
    const int m0 = blockIdx.y * 64;
    const int n0 = blockIdx.x * 64;

    float acc[4][4];
#pragma unroll
    for (int i = 0; i < 4; ++i)
#pragma unroll
        for (int j = 0; j < 4; ++j) acc[i][j] = 0.f;

    const int KT = FEATP / 16;
    for (int kt = 0; kt < KT; ++kt) {
        const int kbase = kt * 16;
        {
            int idx = tid;
            int m  = idx >> 2;
            int k4 = (idx & 3) * 4;
            float4 v = *(const float4*)(g_feat + (size_t)(m0 + m) * FEATP + kbase + k4);
            As[k4 + 0][m] = v.x;
            As[k4 + 1][m] = v.y;
            As[k4 + 2][m] = v.z;
            As[k4 + 3][m] = v.w;
            int kb = idx >> 4;
            int nb = (idx & 15) * 4;
            int kg = kbase + kb;
            float4 w = make_float4(0.f, 0.f, 0.f, 0.f);
            if (kg < FEATR)
                w = *(const float4*)(Wm + (size_t)kg * 512 + n0 + nb);
            *(float4*)&Bs[kb][nb] = w;
        }
        __syncthreads();
#pragma unroll
        for (int kk = 0; kk < 16; ++kk) {
            float a[4], b[4];
            *(float4*)&a[0] = *(const float4*)&As[kk][ty * 4];
            *(float4*)&b[0] = *(const float4*)&Bs[kk][tx * 4];
#pragma unroll
            for (int i = 0; i < 4; ++i)
#pragma unroll
                for (int j = 0; j < 4; ++j)
                    acc[i][j] += a[i] * b[j];
        }
        __syncthreads();
    }

#pragma unroll
    for (int i = 0; i < 4; ++i) {
        int m = m0 + ty * 4 + i;
        int n = n0 + tx * 4;
        float4 r;
        r.x = acc[i][0] + bv[n + 0];
        r.y = acc[i][1] + bv[n + 1];
        r.z = acc[i][2] + bv[n + 2];
        r.w = acc[i][3] + bv[n + 3];
        r.x = r.x > 0.f ? r.x : 0.f;
        r.y = r.y > 0.f ? r.y : 0.f;
        r.z = r.z > 0.f ? r.z : 0.f;
        r.w = r.w > 0.f ? r.w : 0.f;
        *(float4*)(Cout + (size_t)m * 512 + n) = r;
    }
}

__global__ void k_combine(
    const float* __restrict__ head, const float* __restrict__ targetQ,
    const int* __restrict__ action,
    const float* __restrict__ Wsv, const float* __restrict__ bsv,
    const float* __restrict__ Wbv, const float* __restrict__ bbv,
    const float* __restrict__ Wsh, const float* __restrict__ bsh,
    const float* __restrict__ Wbh, const float* __restrict__ bbh,
    float* __restrict__ out, int out_size)
{
    const int b = blockIdx.x;
    const int tid = threadIdx.x;
    float s0 = 0.f, s1 = 0.f, s2 = 0.f, s3 = 0.f, s4 = 0.f, s5 = 0.f;
    for (int k = tid; k < 512; k += 128) {
        float vp = g_vlp[b * 512 + k];
        float qp = g_qlp[b * 512 + k];
        float ve = g_vle[b * 512 + k];
        float qe = g_qle[b * 512 + k];
        s0 += vp * Wsv[k];
        s1 += qp * Wsh[2 * k];
        s2 += qp * Wsh[2 * k + 1];
        s3 += ve * Wbv[k];
        s4 += qe * Wbh[2 * k];
        s5 += qe * Wbh[2 * k + 1];
    }
    __shared__ float red[6][128];
    red[0][tid] = s0; red[1][tid] = s1; red[2][tid] = s2;
    red[3][tid] = s3; red[4][tid] = s4; red[5][tid] = s5;
    __syncthreads();
    for (int off = 64; off > 0; off >>= 1) {
        if (tid < off) {
#pragma unroll
            for (int i = 0; i < 6; ++i) red[i][tid] += red[i][tid + off];
        }
        __syncthreads();
    }
    if (tid == 0) {
        float sellv = red[0][0] + bsv[0];
        float pa0 = red[1][0] + bsh[0];
        float pa1 = red[2][0] + bsh[1];
        float buyv = red[3][0] + bbv[0];
        float ea0 = red[4][0] + bbh[0];
        float ea1 = red[5][0] + bbh[1];
        float pm = 0.5f * (pa0 + pa1);
        float em = 0.5f * (ea0 + ea1);
        float pQ0 = pa0 - pm + sellv;
        float pQ1 = pa1 - pm + sellv;
        float eQ0 = ea0 - em + buyv;
        float eQ1 = ea1 - em + buyv;
        float isp = head[b * 3];
        float Q0, Q1;
        if (isp != 0.f) { Q0 = pQ0; Q1 = eQ1; }
        else            { Q0 = eQ0; Q1 = pQ1; }
        if (out_size >= 1 + 2 * NB) {
            out[1 + 2 * b]     = Q0;
            out[1 + 2 * b + 1] = Q1;
        }
        if (out_size >= 1 + 2 * NB + NB) {
            out[1 + 2 * NB + b] = (Q1 > Q0) ? 1.f : 0.f;
        }
        int a = action[b];
        float iv = (a == 0) ? Q0 : Q1;
        float d = targetQ[b] - iv;
        g_sq[b] = d * d;
    }
}

__global__ void k_loss(float* __restrict__ out, int out_size)
{
    __shared__ float r[256];
    int tid = threadIdx.x;
    r[tid] = g_sq[tid] + g_sq[tid + 256];
    __syncthreads();
    for (int off = 128; off > 0; off >>= 1) {
        if (tid < off) r[tid] += r[tid + off];
        __syncthreads();
    }
    if (tid == 0 && out_size >= 1) out[0] = r[0] * (1.f / 512.f);
}

// ------------------ launch ------------------
extern "C" void kernel_launch(void* const* d_in, const int* in_sizes, int n_in,
                              void* d_out, int out_size)
{
    const float* hist    = (const float*)d_in[0];
    const float* head    = (const float*)d_in[1];
    const float* targetQ = (const float*)d_in[2];
    const int*   action  = (const int*)d_in[3];
    const float* W_lstm  = (const float*)d_in[4];
    const float* b_lstm  = (const float*)d_in[5];
    const float* W3 = (const float*)d_in[6],  *b3 = (const float*)d_in[7];
    const float* W4 = (const float*)d_in[8],  *b4 = (const float*)d_in[9];
    const float* W5 = (const float*)d_in[10], *b5 = (const float*)d_in[11];
    const float* W6 = (const float*)d_in[12], *b6 = (const float*)d_in[13];
    const float* Wsv = (const float*)d_in[14], *bsv = (const float*)d_in[15];
    const float* Wbv = (const float*)d_in[16], *bbv = (const float*)d_in[17];
    const float* Wsh = (const float*)d_in[18], *bsh = (const float*)d_in[19];
    const float* Wbh = (const float*)d_in[20], *bbh = (const float*)d_in[21];
    float* out = (float*)d_out;

    cudaFuncSetAttribute(k_step, cudaFuncAttributeMaxDynamicSharedMemorySize, SMEM_STEP_TOTAL);

    k_init<<<(NB * NH + 255) / 256, 256>>>();
    k_prep_w<<<((size_t)NZ * KTOT + 255) / 256, 256>>>(W_lstm);
    k_prep_x<<<((size_t)NB * NT * NF + 255) / 256, 256>>>(hist);

    dim3 gl(32, 4);
    for (int t = 0; t < NT; ++t)
        k_step<<<gl, 512, SMEM_STEP_TOTAL>>>(b_lstm, t);

    k_feat<<<(NB * FEATP + 255) / 256, 256>>>(head);

    dim3 gh(8, 8, 4);
    k_head_gemm<<<gh, 256>>>(W3, b3, W4, b4, W5, b5, W6, b6);

    k_combine<<<NB, 128>>>(head, targetQ, action,
                           Wsv, bsv, Wbv, bbv, Wsh, bsh, Wbh, bbh,
                           out, out_size);
    k_loss<<<1, 256>>>(out, out_size);
}

// round 8
// speedup vs baseline: 1.1939x; 1.1939x over previous
#include <cuda_runtime.h>
#include <cuda_bf16.h>
#include <cstdint>

#define NB 512      // batch
#define NT 256      // time steps
#define NF 128      // features
#define NH 1024     // hidden
#define NZ 4096     // 4*H
#define KTOT 1152   // NF + NH
#define FEATP 2064  // padded feature length
#define FEATR 2050  // real feature length
#define HBUF ((size_t)NB * NH)

// ------------------ device scratch (no allocation allowed) ------------------
__device__ __nv_bfloat16 g_Wth[(size_t)NZ * KTOT];  // permuted W^T hi  [4096][1152]
__device__ __nv_bfloat16 g_Wtl[(size_t)NZ * KTOT];  // permuted W^T lo
__device__ __nv_bfloat16 g_xh[(size_t)NB * NT * NF];  // history hi
__device__ __nv_bfloat16 g_xl[(size_t)NB * NT * NF];  // history lo
__device__ __nv_bfloat16 g_hh[2 * HBUF];            // h hi (bf16), double-buffered
__device__ __nv_bfloat16 g_hl[2 * HBUF];            // h lo (bf16), double-buffered
__device__ float g_c[NB * NH];                      // c fp32 [m][u]
__device__ float g_hf[NB * NH];                     // h fp32 [m][u]
__device__ float g_feat[NB * FEATP];
__device__ float g_vlp[NB * 512];
__device__ float g_qlp[NB * 512];
__device__ float g_vle[NB * 512];
__device__ float g_qle[NB * 512];
__device__ float g_sq[NB];

// ------------------ helpers ------------------
__device__ __forceinline__ uint32_t smem_u32(const void* p)
{
    uint32_t a;
    asm("{ .reg .u64 t; cvta.to.shared.u64 t, %1; cvt.u32.u64 %0, t; }" : "=r"(a) : "l"(p));
    return a;
}

__device__ __forceinline__ void cpa16(uint32_t s, const void* g)
{
    asm volatile("cp.async.ca.shared.global [%0], [%1], 16;" :: "r"(s), "l"(g) : "memory");
}
#define CP_COMMIT() asm volatile("cp.async.commit_group;" ::: "memory")
#define CP_WAIT1()  asm volatile("cp.async.wait_group 1;" ::: "memory")

#define LDSM4(r0, r1, r2, r3, addr) \
    asm volatile("ldmatrix.sync.aligned.m8n8.x4.shared.b16 {%0,%1,%2,%3}, [%4];" \
                 : "=r"(r0), "=r"(r1), "=r"(r2), "=r"(r3) : "r"(addr))

#define MMA16816(d, a, b) \
    asm volatile("mma.sync.aligned.m16n8k16.row.col.f32.bf16.bf16.f32 " \
                 "{%0,%1,%2,%3}, {%4,%5,%6,%7}, {%8,%9}, {%0,%1,%2,%3};" \
                 : "+f"((d)[0]), "+f"((d)[1]), "+f"((d)[2]), "+f"((d)[3]) \
                 : "r"((a)[0]), "r"((a)[1]), "r"((a)[2]), "r"((a)[3]), \
                   "r"((b)[0]), "r"((b)[1]))

__device__ __forceinline__ uint32_t sw128(uint32_t off) { return off ^ ((off >> 3) & 0x70); }

__device__ __forceinline__ float fsig(float x)
{
    float e = __expf(-x);
    return __fdividef(1.f, 1.f + e);
}
__device__ __forceinline__ float ftanh(float x)
{
    float e = __expf(2.f * x);
    return 1.f - __fdividef(2.f, e + 1.f);
}

// ------------------ prep kernels ------------------
__global__ void k_init()
{
    int i = blockIdx.x * blockDim.x + threadIdx.x;
    if (i < NB * NH) {
        g_c[i] = 0.f;
        g_hh[i] = __float2bfloat16(0.f);   // buffer 0 (read by step 0)
        g_hl[i] = __float2bfloat16(0.f);
    }
}

// Permuted, transposed, split weights: Wt[j][k] = W[k][ (j&3)*1024 + (j>>2) ]
__global__ void k_prep_w(const float* __restrict__ W)
{
    int id = blockIdx.x * blockDim.x + threadIdx.x;
    if (id >= NZ * KTOT) return;
    int j = id / KTOT;
    int k = id - j * KTOT;
    int u = j >> 2;
    int g = j & 3;
    float w = W[(size_t)k * NZ + g * NH + u];
    __nv_bfloat16 hi = __float2bfloat16(w);
    float lo = w - __bfloat162float(hi);
    g_Wth[id] = hi;
    g_Wtl[id] = __float2bfloat16(lo);
}

// Split history into bf16 hi/lo once (same [b][t][f] layout).
__global__ void k_prep_x(const float* __restrict__ hist)
{
    int id = blockIdx.x * blockDim.x + threadIdx.x;
    if (id >= NB * NT * NF) return;
    float v = hist[id];
    __nv_bfloat16 hi = __float2bfloat16(v);
    g_xh[id] = hi;
    g_xl[id] = __float2bfloat16(v - __bfloat162float(hi));
}

// ------------------ fused LSTM step: split-bf16 mma.sync GEMM + cell ------------------
// grid (64 n-tiles, 4 m-tiles) = 256 CTAs -> 2 CTAs/SM. 256 threads (8 warps, 4m x 2n,
// warp tile 32m x 32n). CTA tile: 128 m x 64 cols; col c = u_local*4 + gate; K=1152,
// 18 chunks of 64. Stage: Ahi(16K) Alo(16K) Bhi(8K) Blo(8K) = 48KB; 2 stages = 96KB.
// h is double-buffered across steps: step t reads h[t&1], writes h[(t+1)&1], so the
// cross-CTA read/write race within a launch is impossible.
#define STAGE_BYTES 49152
#define SMEM_STEP_TOTAL (2 * STAGE_BYTES)

__global__ __launch_bounds__(256, 2) void k_step(const float* __restrict__ blstm, int t)
{
    extern __shared__ char smem[];
    const uint32_t sb = smem_u32(smem);
    const int tid = threadIdx.x;
    const int wid = tid >> 5;
    const int lane = tid & 31;
    const int ntile = blockIdx.x;      // 0..63
    const int mtile = blockIdx.y;      // 0..3
    const int m0 = mtile * 128;
    const int j0 = ntile * 64;
    const int u0 = ntile * 16;
    const int wm = wid & 3;    // 4 warp rows of 32 m
    const int wn = wid >> 2;   // 2 warp cols of 32 n

    const size_t hrd = (size_t)(t & 1) * HBUF;         // read buffer
    const size_t hwr = (size_t)((t + 1) & 1) * HBUF;   // write buffer

    float acc[2][4][4];
#pragma unroll
    for (int a = 0; a < 2; ++a)
#pragma unroll
        for (int b = 0; b < 4; ++b)
#pragma unroll
            for (int cc = 0; cc < 4; ++cc) acc[a][b][cc] = 0.f;

    // ---- chunk loader (cp.async): A 1024 units, B 512 units, 12 cpa16/thread ----
    auto load_chunk = [&](int c, uint32_t sbase) {
        const int kb = c * 64;
        const __nv_bfloat16 *aH, *aL;
        size_t astr;
        if (c < 2) {
            size_t base = ((size_t)m0 * NT + t) * NF + kb;
            aH = g_xh + base; aL = g_xl + base; astr = (size_t)NT * NF;
        } else {
            size_t base = hrd + (size_t)m0 * NH + (kb - NF);
            aH = g_hh + base; aL = g_hl + base; astr = NH;
        }
        const __nv_bfloat16* bH = g_Wth + (size_t)j0 * KTOT + kb;
        const __nv_bfloat16* bL = g_Wtl + (size_t)j0 * KTOT + kb;
#pragma unroll
        for (int s4 = 0; s4 < 4; ++s4) {
            int q = tid + s4 * 256;          // 0..1023 : A rows 0..127, segs 0..7
            int row = q >> 3;
            int seg = q & 7;
            uint32_t dsto = sw128((uint32_t)(row * 128 + seg * 16));
            cpa16(sbase + dsto,         aH + (size_t)row * astr + seg * 8);
            cpa16(sbase + 16384 + dsto, aL + (size_t)row * astr + seg * 8);
        }
#pragma unroll
        for (int s4 = 0; s4 < 2; ++s4) {
            int q = tid + s4 * 256;          // 0..511 : B rows 0..63, segs 0..7
            int row = q >> 3;
            int seg = q & 7;
            uint32_t dsto = sw128((uint32_t)(row * 128 + seg * 16));
            cpa16(sbase + 32768 + dsto, bH + (size_t)row * KTOT + seg * 8);
            cpa16(sbase + 40960 + dsto, bL + (size_t)row * KTOT + seg * 8);
        }
    };

    // ldmatrix lane addressing pieces
    const int lr = lane & 7;
    const int lg8 = (lane >> 3) & 1;
    const int lg16 = (lane >> 4) & 1;

    load_chunk(0, sb);
    CP_COMMIT();

    for (int c = 0; c < 18; ++c) {
        if (c + 1 < 18) load_chunk(c + 1, sb + (uint32_t)((c + 1) & 1) * STAGE_BYTES);
        CP_COMMIT();
        CP_WAIT1();
        __syncthreads();

        const uint32_t base = sb + (uint32_t)(c & 1) * STAGE_BYTES;
        const uint32_t aHb = base, aLb = base + 16384;
        const uint32_t bHb = base + 32768, bLb = base + 40960;

#pragma unroll
        for (int k16 = 0; k16 < 4; ++k16) {
            const int kby = k16 * 32;  // byte offset of k16*16 bf16
            uint32_t bh[4][2], bl[4][2];
#pragma unroll
            for (int p = 0; p < 2; ++p) {   // two 16-row n groups
                uint32_t roff = (uint32_t)((wn * 32 + p * 16 + lg16 * 8 + lr) * 128
                                           + kby + lg8 * 16);
                uint32_t sw = sw128(roff);
                uint32_t r0, r1, r2, r3;
                LDSM4(r0, r1, r2, r3, bHb + sw);
                bh[p * 2][0] = r0; bh[p * 2][1] = r1; bh[p * 2 + 1][0] = r2; bh[p * 2 + 1][1] = r3;
                LDSM4(r0, r1, r2, r3, bLb + sw);
                bl[p * 2][0] = r0; bl[p * 2][1] = r1; bl[p * 2 + 1][0] = r2; bl[p * 2 + 1][1] = r3;
            }
#pragma unroll
            for (int mt = 0; mt < 2; ++mt) {
                uint32_t roff = (uint32_t)((wm * 32 + mt * 16 + lg8 * 8 + lr) * 128
                                           + kby + lg16 * 16);
                uint32_t sw = sw128(roff);
                uint32_t ah[4], al[4];
                LDSM4(ah[0], ah[1], ah[2], ah[3], aHb + sw);
                LDSM4(al[0], al[1], al[2], al[3], aLb + sw);
#pragma unroll
                for (int nt = 0; nt < 4; ++nt) {
                    MMA16816(acc[mt][nt], ah, bh[nt]);
                    MMA16816(acc[mt][nt], ah, bl[nt]);
                    MMA16816(acc[mt][nt], al, bh[nt]);
                }
            }
        }
        __syncthreads();   // protect stage before refill next iter
    }

    // ---- fused cell epilogue (register accumulators) ----
    const int g = lane >> 2;
    const int tq = lane & 3;
    const bool even = (tq & 1) == 0;
#pragma unroll
    for (int mt = 0; mt < 2; ++mt) {
#pragma unroll
        for (int nt = 0; nt < 4; ++nt) {
            float c0 = acc[mt][nt][0], c1 = acc[mt][nt][1];
            float c2 = acc[mt][nt][2], c3 = acc[mt][nt][3];
            float s0 = even ? c2 : c0;
            float s1 = even ? c3 : c1;
            float r0 = __shfl_xor_sync(0xffffffffu, s0, 1);
            float r1 = __shfl_xor_sync(0xffffffffu, s1, 1);
            float zi, zj, zf, zo;
            int row;
            if (even) { row = g;     zi = c0; zj = c1; zf = r0; zo = r1; }
            else      { row = g + 8; zi = r0; zj = r1; zf = c2; zo = c3; }
            int u = u0 + wn * 8 + nt * 2 + (tq >> 1);
            int m = m0 + wm * 32 + mt * 16 + row;
            float bi = blstm[u];
            float bj = blstm[NH + u];
            float bf_ = blstm[2 * NH + u];
            float bo = blstm[3 * NH + u];
            size_t idx = (size_t)m * NH + u;
            float cold = g_c[idx];
            float cn = fsig(zf + bf_ + 1.f) * cold + fsig(zi + bi) * ftanh(zj + bj);
            float h = fsig(zo + bo) * ftanh(cn);
            g_c[idx] = cn;
            g_hf[idx] = h;
            __nv_bfloat16 hb = __float2bfloat16(h);
            g_hh[hwr + idx] = hb;
            g_hl[hwr + idx] = __float2bfloat16(h - __bfloat162float(hb));
        }
    }
}

// ------------------ feature assembly + head MLPs ------------------
__global__ void k_feat(const float* __restrict__ head)
{
    int idx = blockIdx.x * blockDim.x + threadIdx.x;
    if (idx >= NB * FEATP) return;
    int b = idx / FEATP;
    int k = idx - b * FEATP;
    float v;
    if (k < 2)            v = head[b * 3 + 1 + k];
    else if (k < 1026)    v = g_c[b * NH + (k - 2)];
    else if (k < 2050)    v = g_hf[b * NH + (k - 1026)];
    else                  v = 0.f;
    g_feat[idx] = v;
}

__global__ __launch_bounds__(256) void k_head_gemm(
    const float* __restrict__ W3, const float* __restrict__ b3,
    const float* __restrict__ W4, const float* __restrict__ b4,
    const float* __restrict__ W5, const float* __restrict__ b5,
    const float* __restrict__ W6, const float* __restrict__ b6)
{
    const int which = blockIdx.z;
    const float* Wm = (which == 0) ? W3 : (which == 1) ? W4 : (which == 2) ? W5 : W6;
    const float* bv = (which == 0) ? b3 : (which == 1) ? b4 : (which == 2) ? b5 : b6;
    float* Cout = (which == 0) ? g_vlp : (which == 1) ? g_qlp : (which == 2) ? g_vle : g_qle;

    __shared__ float As[16][64];
    __shared__ float Bs[16][64];
    const int tid = threadIdx.x;
    const int tx = tid & 15;
    const int ty = tid >> 4;
    const int m0 = blockIdx.y * 64;
    const int n0 = blockIdx.x * 64;

    float acc[4][4];
#pragma unroll
    for (int i = 0; i < 4; ++i)
#pragma unroll
        for (int j = 0; j < 4; ++j) acc[i][j] = 0.f;

    const int KT = FEATP / 16;
    for (int kt = 0; kt < KT; ++kt) {
        const int kbase = kt * 16;
        {
            int idx = tid;
            int m  = idx >> 2;
            int k4 = (idx & 3) * 4;
            float4 v = *(const float4*)(g_feat + (size_t)(m0 + m) * FEATP + kbase + k4);
            As[k4 + 0][m] = v.x;
            As[k4 + 1][m] = v.y;
            As[k4 + 2][m] = v.z;
            As[k4 + 3][m] = v.w;
            int kb = idx >> 4;
            int nb = (idx & 15) * 4;
            int kg = kbase + kb;
            float4 w = make_float4(0.f, 0.f, 0.f, 0.f);
            if (kg < FEATR)
                w = *(const float4*)(Wm + (size_t)kg * 512 + n0 + nb);
            *(float4*)&Bs[kb][nb] = w;
        }
        __syncthreads();
#pragma unroll
        for (int kk = 0; kk < 16; ++kk) {
            float a[4], b[4];
            *(float4*)&a[0] = *(const float4*)&As[kk][ty * 4];
            *(float4*)&b[0] = *(const float4*)&Bs[kk][tx * 4];
#pragma unroll
            for (int i = 0; i < 4; ++i)
#pragma unroll
                for (int j = 0; j < 4; ++j)
                    acc[i][j] += a[i] * b[j];
        }
        __syncthreads();
    }

#pragma unroll
    for (int i = 0; i < 4; ++i) {
        int m = m0 + ty * 4 + i;
        int n = n0 + tx * 4;
        float4 r;
        r.x = acc[i][0] + bv[n + 0];
        r.y = acc[i][1] + bv[n + 1];
        r.z = acc[i][2] + bv[n + 2];
        r.w = acc[i][3] + bv[n + 3];
        r.x = r.x > 0.f ? r.x : 0.f;
        r.y = r.y > 0.f ? r.y : 0.f;
        r.z = r.z > 0.f ? r.z : 0.f;
        r.w = r.w > 0.f ? r.w : 0.f;
        *(float4*)(Cout + (size_t)m * 512 + n) = r;
    }
}

__global__ void k_combine(
    const float* __restrict__ head, const float* __restrict__ targetQ,
    const int* __restrict__ action,
    const float* __restrict__ Wsv, const float* __restrict__ bsv,
    const float* __restrict__ Wbv, const float* __restrict__ bbv,
    const float* __restrict__ Wsh, const float* __restrict__ bsh,
    const float* __restrict__ Wbh, const float* __restrict__ bbh,
    float* __restrict__ out, int out_size)
{
    const int b = blockIdx.x;
    const int tid = threadIdx.x;
    float s0 = 0.f, s1 = 0.f, s2 = 0.f, s3 = 0.f, s4 = 0.f, s5 = 0.f;
    for (int k = tid; k < 512; k += 128) {
        float vp = g_vlp[b * 512 + k];
        float qp = g_qlp[b * 512 + k];
        float ve = g_vle[b * 512 + k];
        float qe = g_qle[b * 512 + k];
        s0 += vp * Wsv[k];
        s1 += qp * Wsh[2 * k];
        s2 += qp * Wsh[2 * k + 1];
        s3 += ve * Wbv[k];
        s4 += qe * Wbh[2 * k];
        s5 += qe * Wbh[2 * k + 1];
    }
    __shared__ float red[6][128];
    red[0][tid] = s0; red[1][tid] = s1; red[2][tid] = s2;
    red[3][tid] = s3; red[4][tid] = s4; red[5][tid] = s5;
    __syncthreads();
    for (int off = 64; off > 0; off >>= 1) {
        if (tid < off) {
#pragma unroll
            for (int i = 0; i < 6; ++i) red[i][tid] += red[i][tid + off];
        }
        __syncthreads();
    }
    if (tid == 0) {
        float sellv = red[0][0] + bsv[0];
        float pa0 = red[1][0] + bsh[0];
        float pa1 = red[2][0] + bsh[1];
        float buyv = red[3][0] + bbv[0];
        float ea0 = red[4][0] + bbh[0];
        float ea1 = red[5][0] + bbh[1];
        float pm = 0.5f * (pa0 + pa1);
        float em = 0.5f * (ea0 + ea1);
        float pQ0 = pa0 - pm + sellv;
        float pQ1 = pa1 - pm + sellv;
        float eQ0 = ea0 - em + buyv;
        float eQ1 = ea1 - em + buyv;
        float isp = head[b * 3];
        float Q0, Q1;
        if (isp != 0.f) { Q0 = pQ0; Q1 = eQ1; }
        else            { Q0 = eQ0; Q1 = pQ1; }
        if (out_size >= 1 + 2 * NB) {
            out[1 + 2 * b]     = Q0;
            out[1 + 2 * b + 1] = Q1;
        }
        if (out_size >= 1 + 2 * NB + NB) {
            out[1 + 2 * NB + b] = (Q1 > Q0) ? 1.f : 0.f;
        }
        int a = action[b];
        float iv = (a == 0) ? Q0 : Q1;
        float d = targetQ[b] - iv;
        g_sq[b] = d * d;
    }
}

__global__ void k_loss(float* __restrict__ out, int out_size)
{
    __shared__ float r[256];
    int tid = threadIdx.x;
    r[tid] = g_sq[tid] + g_sq[tid + 256];
    __syncthreads();
    for (int off = 128; off > 0; off >>= 1) {
        if (tid < off) r[tid] += r[tid + off];
        __syncthreads();
    }
    if (tid == 0 && out_size >= 1) out[0] = r[0] * (1.f / 512.f);
}

// ------------------ launch ------------------
extern "C" void kernel_launch(void* const* d_in, const int* in_sizes, int n_in,
                              void* d_out, int out_size)
{
    const float* hist    = (const float*)d_in[0];
    const float* head    = (const float*)d_in[1];
    const float* targetQ = (const float*)d_in[2];
    const int*   action  = (const int*)d_in[3];
    const float* W_lstm  = (const float*)d_in[4];
    const float* b_lstm  = (const float*)d_in[5];
    const float* W3 = (const float*)d_in[6],  *b3 = (const float*)d_in[7];
    const float* W4 = (const float*)d_in[8],  *b4 = (const float*)d_in[9];
    const float* W5 = (const float*)d_in[10], *b5 = (const float*)d_in[11];
    const float* W6 = (const float*)d_in[12], *b6 = (const float*)d_in[13];
    const float* Wsv = (const float*)d_in[14], *bsv = (const float*)d_in[15];
    const float* Wbv = (const float*)d_in[16], *bbv = (const float*)d_in[17];
    const float* Wsh = (const float*)d_in[18], *bsh = (const float*)d_in[19];
    const float* Wbh = (const float*)d_in[20], *bbh = (const float*)d_in[21];
    float* out = (float*)d_out;

    cudaFuncSetAttribute(k_step, cudaFuncAttributeMaxDynamicSharedMemorySize, SMEM_STEP_TOTAL);

    k_init<<<(NB * NH + 255) / 256, 256>>>();
    k_prep_w<<<((size_t)NZ * KTOT + 255) / 256, 256>>>(W_lstm);
    k_prep_x<<<((size_t)NB * NT * NF + 255) / 256, 256>>>(hist);

    dim3 gl(64, 4);  // 256 CTAs -> 2 per SM
    for (int t = 0; t < NT; ++t)
        k_step<<<gl, 256, SMEM_STEP_TOTAL>>>(b_lstm, t);

    k_feat<<<(NB * FEATP + 255) / 256, 256>>>(head);

    dim3 gh(8, 8, 4);
    k_head_gemm<<<gh, 256>>>(W3, b3, W4, b4, W5, b5, W6, b6);

    k_combine<<<NB, 128>>>(head, targetQ, action,
                           Wsv, bsv, Wbv, bbv, Wsh, bsh, Wbh, bbh,
                           out, out_size);
    k_loss<<<1, 256>>>(out, out_size);
}

// round 9
// speedup vs baseline: 1.3221x; 1.1074x over previous
#include <cuda_runtime.h>
#include <cuda_bf16.h>
#include <cstdint>

#define NB 512      // batch
#define NT 256      // time steps
#define NF 128      // features
#define NH 1024     // hidden
#define NZ 4096     // 4*H
#define KTOT 1152   // NF + NH
#define FEATP 2064  // padded feature length
#define FEATR 2050  // real feature length
#define HFRAG ((size_t)NB * NH)

// ------------------ device scratch (no allocation allowed) ------------------
// All MMA operands stored in PTX m16n8k16 fragment layout (see prep kernels).
__device__ __align__(16) __nv_bfloat16 g_Wfh[(size_t)NZ * KTOT];   // W^T hi, B-frag layout
__device__ __align__(16) __nv_bfloat16 g_Wfl[(size_t)NZ * KTOT];   // W^T lo
__device__ __align__(16) __nv_bfloat16 g_xfh[(size_t)NB * NT * NF]; // x hi, A-frag layout
__device__ __align__(16) __nv_bfloat16 g_xfl[(size_t)NB * NT * NF]; // x lo
__device__ __align__(16) __nv_bfloat16 g_hfh[2 * HFRAG];           // h hi, A-frag, dbl-buffered
__device__ __align__(16) __nv_bfloat16 g_hfl[2 * HFRAG];           // h lo
__device__ float g_c[NB * NH];
__device__ float g_hf[NB * NH];
__device__ float g_feat[NB * FEATP];
__device__ float g_vlp[NB * 512];
__device__ float g_qlp[NB * 512];
__device__ float g_vle[NB * 512];
__device__ float g_qle[NB * 512];
__device__ float g_sq[NB];

// ------------------ helpers ------------------
#define MMA16816(d, a, b) \
    asm volatile("mma.sync.aligned.m16n8k16.row.col.f32.bf16.bf16.f32 " \
                 "{%0,%1,%2,%3}, {%4,%5,%6,%7}, {%8,%9}, {%0,%1,%2,%3};" \
                 : "+f"((d)[0]), "+f"((d)[1]), "+f"((d)[2]), "+f"((d)[3]) \
                 : "r"((a)[0]), "r"((a)[1]), "r"((a)[2]), "r"((a)[3]), \
                   "r"((b)[0]), "r"((b)[1]))

__device__ __forceinline__ float fsig(float x)
{
    float e = __expf(-x);
    return __fdividef(1.f, 1.f + e);
}
__device__ __forceinline__ float ftanh(float x)
{
    float e = __expf(2.f * x);
    return 1.f - __fdividef(2.f, e + 1.f);
}

// ------------------ prep kernels ------------------
__global__ void k_init()
{
    int i = blockIdx.x * blockDim.x + threadIdx.x;
    if (i < NB * NH) {
        g_c[i] = 0.f;
        g_hfh[i] = __float2bfloat16(0.f);   // h buffer 0 (read by step 0); zeros are zeros in any layout
        g_hfl[i] = __float2bfloat16(0.f);
    }
}

// W -> permuted (col j = u*4+gate), split hi/lo, stored in B-fragment layout:
// tile pair (J = j/16, K16 = k/16), lane = (j%8)*4 + ((k%8)/2),
// reg = ((j%16)/8)*2 + (k%16)/8, halfword = k%2.
// Block of 512B per (J,K16); blocks ordered [J][K16] (k16 contiguous for streaming).
__global__ void k_prep_w(const float* __restrict__ W)
{
    int id = blockIdx.x * blockDim.x + threadIdx.x;
    if (id >= NZ * KTOT) return;
    int j = id / KTOT;
    int k = id - j * KTOT;
    int u = j >> 2;
    int g = j & 3;
    float w = W[(size_t)k * NZ + g * NH + u];
    __nv_bfloat16 hi = __float2bfloat16(w);
    float lo = w - __bfloat162float(hi);
    int J = j >> 4;
    int n16 = j & 15;
    int K16 = k >> 4;
    int kk = k & 15;
    int lane = (n16 & 7) * 4 + ((kk & 7) >> 1);
    int reg = (n16 >> 3) * 2 + (kk >> 3);
    int half = kk & 1;
    size_t out = ((size_t)J * 72 + K16) * 256 + lane * 8 + reg * 2 + half;
    g_Wfh[out] = hi;
    g_Wfl[out] = __float2bfloat16(lo);
}

// history -> split hi/lo in A-fragment layout:
// tile (mb = b/16, t, kb = f/16): lane = (b%8)*4 + ((f%8)/2),
// reg = ((b%16)/8) + 2*((f%16)/8), halfword = f%2. Blocks ordered [mb][t][kb].
__global__ void k_prep_x(const float* __restrict__ hist)
{
    int id = blockIdx.x * blockDim.x + threadIdx.x;
    if (id >= NB * NT * NF) return;
    int b = id / (NT * NF);
    int r = id - b * (NT * NF);
    int t = r / NF;
    int f = r - t * NF;
    float v = hist[id];
    __nv_bfloat16 hi = __float2bfloat16(v);
    float lo = v - __bfloat162float(hi);
    int mb = b >> 4, row = b & 15;
    int kb = f >> 4, kk = f & 15;
    int lane = (row & 7) * 4 + ((kk & 7) >> 1);
    int reg = (row >> 3) + 2 * (kk >> 3);
    int half = kk & 1;
    size_t out = ((size_t)(mb * NT + t) * 8 + kb) * 256 + lane * 8 + reg * 2 + half;
    g_xfh[out] = hi;
    g_xfl[out] = __float2bfloat16(lo);
}

// ------------------ fused LSTM step: smem-free fragment-direct GEMM + cell ------------------
// grid (64 n-tiles, 4 m-tiles), 256 threads (8 warps, 4m x 2n, warp tile 32m x 32n).
// NO shared memory, NO barriers: every warp loads its operand fragments straight from
// gmem (fragment-layout arrays above) with LDG.128 and runs independently.
// K loop: 72 k16 slices; per slice 8 LDG.128 + 24 MMA; double-buffered in registers.
__global__ __launch_bounds__(256, 2) void k_step(const float* __restrict__ blstm, int t)
{
    const int tid = threadIdx.x;
    const int wid = tid >> 5;
    const int lane = tid & 31;
    const int ntile = blockIdx.x;      // 0..63
    const int mtile = blockIdx.y;      // 0..3
    const int wm = wid & 3;            // 4 warp rows of 32 m
    const int wn = wid >> 2;           // 2 warp cols of 32 n
    const int u0 = ntile * 16;
    const int m0 = mtile * 128;

    const size_t hrd = (size_t)(t & 1) * HFRAG;        // h read buffer
    const size_t hwr = (size_t)((t + 1) & 1) * HFRAG;  // h write buffer

    float acc[2][4][4];
#pragma unroll
    for (int a = 0; a < 2; ++a)
#pragma unroll
        for (int b = 0; b < 4; ++b)
#pragma unroll
            for (int cc = 0; cc < 4; ++cc) acc[a][b][cc] = 0.f;

    const int mbG0 = mtile * 8 + wm * 2;
    const int J0 = ntile * 4 + wn * 2;
    const int lo8 = lane * 8;

    const __nv_bfloat16 *pXh[2], *pXl[2], *pHh[2], *pHl[2];
#pragma unroll
    for (int mt = 0; mt < 2; ++mt) {
        size_t xb = ((size_t)((mbG0 + mt) * NT + t) * 8) * 256 + lo8;
        pXh[mt] = g_xfh + xb;
        pXl[mt] = g_xfl + xb;
        size_t hb = hrd + ((size_t)(mbG0 + mt) * 64) * 256 + lo8;
        pHh[mt] = g_hfh + hb;
        pHl[mt] = g_hfl + hb;
    }
    const __nv_bfloat16 *pBh[2], *pBl[2];
#pragma unroll
    for (int p = 0; p < 2; ++p) {
        size_t wb = ((size_t)(J0 + p) * 72) * 256 + lo8;
        pBh[p] = g_Wfh + wb;
        pBl[p] = g_Wfl + wb;
    }

    uint32_t Ah[2][2][4], Al[2][2][4], Bh[2][2][4], Bl[2][2][4];  // [buf][mt|ntp][reg]

    auto ldAB = [&](int s, int buf) {
        if (s < 8) {
#pragma unroll
            for (int mt = 0; mt < 2; ++mt) {
                uint4 vh = *(const uint4*)(pXh[mt] + (size_t)s * 256);
                uint4 vl = *(const uint4*)(pXl[mt] + (size_t)s * 256);
                Ah[buf][mt][0] = vh.x; Ah[buf][mt][1] = vh.y; Ah[buf][mt][2] = vh.z; Ah[buf][mt][3] = vh.w;
                Al[buf][mt][0] = vl.x; Al[buf][mt][1] = vl.y; Al[buf][mt][2] = vl.z; Al[buf][mt][3] = vl.w;
            }
        } else {
#pragma unroll
            for (int mt = 0; mt < 2; ++mt) {
                uint4 vh = *(const uint4*)(pHh[mt] + (size_t)(s - 8) * 256);
                uint4 vl = *(const uint4*)(pHl[mt] + (size_t)(s - 8) * 256);
                Ah[buf][mt][0] = vh.x; Ah[buf][mt][1] = vh.y; Ah[buf][mt][2] = vh.z; Ah[buf][mt][3] = vh.w;
                Al[buf][mt][0] = vl.x; Al[buf][mt][1] = vl.y; Al[buf][mt][2] = vl.z; Al[buf][mt][3] = vl.w;
            }
        }
#pragma unroll
        for (int p = 0; p < 2; ++p) {
            uint4 vh = *(const uint4*)(pBh[p] + (size_t)s * 256);
            uint4 vl = *(const uint4*)(pBl[p] + (size_t)s * 256);
            Bh[buf][p][0] = vh.x; Bh[buf][p][1] = vh.y; Bh[buf][p][2] = vh.z; Bh[buf][p][3] = vh.w;
            Bl[buf][p][0] = vl.x; Bl[buf][p][1] = vl.y; Bl[buf][p][2] = vl.z; Bl[buf][p][3] = vl.w;
        }
    };

    auto domma = [&](int buf) {
#pragma unroll
        for (int mt = 0; mt < 2; ++mt)
#pragma unroll
            for (int nt = 0; nt < 4; ++nt) {
                uint32_t* bph = &Bh[buf][nt >> 1][(nt & 1) * 2];
                uint32_t* bpl = &Bl[buf][nt >> 1][(nt & 1) * 2];
                MMA16816(acc[mt][nt], Ah[buf][mt], bph);
                MMA16816(acc[mt][nt], Ah[buf][mt], bpl);
                MMA16816(acc[mt][nt], Al[buf][mt], bph);
            }
    };

    ldAB(0, 0);
    ldAB(1, 1);
#pragma unroll 1
    for (int s = 0; s < 72; s += 2) {
        domma(0);
        if (s + 2 < 72) ldAB(s + 2, 0);
        domma(1);
        if (s + 3 < 72) ldAB(s + 3, 1);
    }

    // ---- fused cell epilogue (register accumulators) ----
    const int g = lane >> 2;
    const int tq = lane & 3;
    const bool even = (tq & 1) == 0;
#pragma unroll
    for (int mt = 0; mt < 2; ++mt) {
#pragma unroll
        for (int nt = 0; nt < 4; ++nt) {
            float c0 = acc[mt][nt][0], c1 = acc[mt][nt][1];
            float c2 = acc[mt][nt][2], c3 = acc[mt][nt][3];
            float s0 = even ? c2 : c0;
            float s1 = even ? c3 : c1;
            float r0 = __shfl_xor_sync(0xffffffffu, s0, 1);
            float r1 = __shfl_xor_sync(0xffffffffu, s1, 1);
            float zi, zj, zf, zo;
            int row;
            if (even) { row = g;     zi = c0; zj = c1; zf = r0; zo = r1; }
            else      { row = g + 8; zi = r0; zj = r1; zf = c2; zo = c3; }
            int u = u0 + wn * 8 + nt * 2 + (tq >> 1);
            int m = m0 + wm * 32 + mt * 16 + row;
            float bi = blstm[u];
            float bj = blstm[NH + u];
            float bf_ = blstm[2 * NH + u];
            float bo = blstm[3 * NH + u];
            size_t idx = (size_t)m * NH + u;
            float cold = g_c[idx];
            float cn = fsig(zf + bf_ + 1.f) * cold + fsig(zi + bi) * ftanh(zj + bj);
            float h = fsig(zo + bo) * ftanh(cn);
            g_c[idx] = cn;
            g_hf[idx] = h;
            __nv_bfloat16 hb = __float2bfloat16(h);
            __nv_bfloat16 lb = __float2bfloat16(h - __bfloat162float(hb));
            // store h into A-fragment layout for the next step
            int mb = m >> 4, rowb = m & 15, kb = u >> 4, kk = u & 15;
            int lane2 = (rowb & 7) * 4 + ((kk & 7) >> 1);
            int reg = (rowb >> 3) + 2 * (kk >> 3);
            int half = kk & 1;
            size_t fo = ((size_t)(mb * 64 + kb)) * 256 + lane2 * 8 + reg * 2 + half;
            g_hfh[hwr + fo] = hb;
            g_hfl[hwr + fo] = lb;
        }
    }
}

// ------------------ feature assembly + head MLPs ------------------
__global__ void k_feat(const float* __restrict__ head)
{
    int idx = blockIdx.x * blockDim.x + threadIdx.x;
    if (idx >= NB * FEATP) return;
    int b = idx / FEATP;
    int k = idx - b * FEATP;
    float v;
    if (k < 2)            v = head[b * 3 + 1 + k];
    else if (k < 1026)    v = g_c[b * NH + (k - 2)];
    else if (k < 2050)    v = g_hf[b * NH + (k - 1026)];
    else                  v = 0.f;
    g_feat[idx] = v;
}

__global__ __launch_bounds__(256) void k_head_gemm(
    const float* __restrict__ W3, const float* __restrict__ b3,
    const float* __restrict__ W4, const float* __restrict__ b4,
    const float* __restrict__ W5, const float* __restrict__ b5,
    const float* __restrict__ W6, const float* __restrict__ b6)
{
    const int which = blockIdx.z;
    const float* Wm = (which == 0) ? W3 : (which == 1) ? W4 : (which == 2) ? W5 : W6;
    const float* bv = (which == 0) ? b3 : (which == 1) ? b4 : (which == 2) ? b5 : b6;
    float* Cout = (which == 0) ? g_vlp : (which == 1) ? g_qlp : (which == 2) ? g_vle : g_qle;

    __shared__ float As[16][64];
    __shared__ float Bs[16][64];
    const int tid = threadIdx.x;
    const int tx = tid & 15;
    const int ty = tid >> 4;
    const int m0 = blockIdx.y * 64;
    const int n0 = blockIdx.x * 64;

    float acc[4][4];
#pragma unroll
    for (int i = 0; i < 4; ++i)
#pragma unroll
        for (int j = 0; j < 4; ++j) acc[i][j] = 0.f;

    const int KT = FEATP / 16;
    for (int kt = 0; kt < KT; ++kt) {
        const int kbase = kt * 16;
        {
            int idx = tid;
            int m  = idx >> 2;
            int k4 = (idx & 3) * 4;
            float4 v = *(const float4*)(g_feat + (size_t)(m0 + m) * FEATP + kbase + k4);
            As[k4 + 0][m] = v.x;
            As[k4 + 1][m] = v.y;
            As[k4 + 2][m] = v.z;
            As[k4 + 3][m] = v.w;
            int kb = idx >> 4;
            int nb = (idx & 15) * 4;
            int kg = kbase + kb;
            float4 w = make_float4(0.f, 0.f, 0.f, 0.f);
            if (kg < FEATR)
                w = *(const float4*)(Wm + (size_t)kg * 512 + n0 + nb);
            *(float4*)&Bs[kb][nb] = w;
        }
        __syncthreads();
#pragma unroll
        for (int kk = 0; kk < 16; ++kk) {
            float a[4], b[4];
            *(float4*)&a[0] = *(const float4*)&As[kk][ty * 4];
            *(float4*)&b[0] = *(const float4*)&Bs[kk][tx * 4];
#pragma unroll
            for (int i = 0; i < 4; ++i)
#pragma unroll
                for (int j = 0; j < 4; ++j)
                    acc[i][j] += a[i] * b[j];
        }
        __syncthreads();
    }

#pragma unroll
    for (int i = 0; i < 4; ++i) {
        int m = m0 + ty * 4 + i;
        int n = n0 + tx * 4;
        float4 r;
        r.x = acc[i][0] + bv[n + 0];
        r.y = acc[i][1] + bv[n + 1];
        r.z = acc[i][2] + bv[n + 2];
        r.w = acc[i][3] + bv[n + 3];
        r.x = r.x > 0.f ? r.x : 0.f;
        r.y = r.y > 0.f ? r.y : 0.f;
        r.z = r.z > 0.f ? r.z : 0.f;
        r.w = r.w > 0.f ? r.w : 0.f;
        *(float4*)(Cout + (size_t)m * 512 + n) = r;
    }
}

__global__ void k_combine(
    const float* __restrict__ head, const float* __restrict__ targetQ,
    const int* __restrict__ action,
    const float* __restrict__ Wsv, const float* __restrict__ bsv,
    const float* __restrict__ Wbv, const float* __restrict__ bbv,
    const float* __restrict__ Wsh, const float* __restrict__ bsh,
    const float* __restrict__ Wbh, const float* __restrict__ bbh,
    float* __restrict__ out, int out_size)
{
    const int b = blockIdx.x;
    const int tid = threadIdx.x;
    float s0 = 0.f, s1 = 0.f, s2 = 0.f, s3 = 0.f, s4 = 0.f, s5 = 0.f;
    for (int k = tid; k < 512; k += 128) {
        float vp = g_vlp[b * 512 + k];
        float qp = g_qlp[b * 512 + k];
        float ve = g_vle[b * 512 + k];
        float qe = g_qle[b * 512 + k];
        s0 += vp * Wsv[k];
        s1 += qp * Wsh[2 * k];
        s2 += qp * Wsh[2 * k + 1];
        s3 += ve * Wbv[k];
        s4 += qe * Wbh[2 * k];
        s5 += qe * Wbh[2 * k + 1];
    }
    __shared__ float red[6][128];
    red[0][tid] = s0; red[1][tid] = s1; red[2][tid] = s2;
    red[3][tid] = s3; red[4][tid] = s4; red[5][tid] = s5;
    __syncthreads();
    for (int off = 64; off > 0; off >>= 1) {
        if (tid < off) {
#pragma unroll
            for (int i = 0; i < 6; ++i) red[i][tid] += red[i][tid + off];
        }
        __syncthreads();
    }
    if (tid == 0) {
        float sellv = red[0][0] + bsv[0];
        float pa0 = red[1][0] + bsh[0];
        float pa1 = red[2][0] + bsh[1];
        float buyv = red[3][0] + bbv[0];
        float ea0 = red[4][0] + bbh[0];
        float ea1 = red[5][0] + bbh[1];
        float pm = 0.5f * (pa0 + pa1);
        float em = 0.5f * (ea0 + ea1);
        float pQ0 = pa0 - pm + sellv;
        float pQ1 = pa1 - pm + sellv;
        float eQ0 = ea0 - em + buyv;
        float eQ1 = ea1 - em + buyv;
        float isp = head[b * 3];
        float Q0, Q1;
        if (isp != 0.f) { Q0 = pQ0; Q1 = eQ1; }
        else            { Q0 = eQ0; Q1 = pQ1; }
        if (out_size >= 1 + 2 * NB) {
            out[1 + 2 * b]     = Q0;
            out[1 + 2 * b + 1] = Q1;
        }
        if (out_size >= 1 + 2 * NB + NB) {
            out[1 + 2 * NB + b] = (Q1 > Q0) ? 1.f : 0.f;
        }
        int a = action[b];
        float iv = (a == 0) ? Q0 : Q1;
        float d = targetQ[b] - iv;
        g_sq[b] = d * d;
    }
}

__global__ void k_loss(float* __restrict__ out, int out_size)
{
    __shared__ float r[256];
    int tid = threadIdx.x;
    r[tid] = g_sq[tid] + g_sq[tid + 256];
    __syncthreads();
    for (int off = 128; off > 0; off >>= 1) {
        if (tid < off) r[tid] += r[tid + off];
        __syncthreads();
    }
    if (tid == 0 && out_size >= 1) out[0] = r[0] * (1.f / 512.f);
}

// ------------------ launch ------------------
extern "C" void kernel_launch(void* const* d_in, const int* in_sizes, int n_in,
                              void* d_out, int out_size)
{
    const float* hist    = (const float*)d_in[0];
    const float* head    = (const float*)d_in[1];
    const float* targetQ = (const float*)d_in[2];
    const int*   action  = (const int*)d_in[3];
    const float* W_lstm  = (const float*)d_in[4];
    const float* b_lstm  = (const float*)d_in[5];
    const float* W3 = (const float*)d_in[6],  *b3 = (const float*)d_in[7];
    const float* W4 = (const float*)d_in[8],  *b4 = (const float*)d_in[9];
    const float* W5 = (const float*)d_in[10], *b5 = (const float*)d_in[11];
    const float* W6 = (const float*)d_in[12], *b6 = (const float*)d_in[13];
    const float* Wsv = (const float*)d_in[14], *bsv = (const float*)d_in[15];
    const float* Wbv = (const float*)d_in[16], *bbv = (const float*)d_in[17];
    const float* Wsh = (const float*)d_in[18], *bsh = (const float*)d_in[19];
    const float* Wbh = (const float*)d_in[20], *bbh = (const float*)d_in[21];
    float* out = (float*)d_out;

    k_init<<<(NB * NH + 255) / 256, 256>>>();
    k_prep_w<<<((size_t)NZ * KTOT + 255) / 256, 256>>>(W_lstm);
    k_prep_x<<<((size_t)NB * NT * NF + 255) / 256, 256>>>(hist);

    dim3 gl(64, 4);  // 256 CTAs, no smem, no barriers
    for (int t = 0; t < NT; ++t)
        k_step<<<gl, 256>>>(b_lstm, t);

    k_feat<<<(NB * FEATP + 255) / 256, 256>>>(head);

    dim3 gh(8, 8, 4);
    k_head_gemm<<<gh, 256>>>(W3, b3, W4, b4, W5, b5, W6, b6);

    k_combine<<<NB, 128>>>(head, targetQ, action,
                           Wsv, bsv, Wbv, bbv, Wsh, bsh, Wbh, bbh,
                           out, out_size);
    k_loss<<<1, 256>>>(out, out_size);
}

// round 10
// speedup vs baseline: 1.3863x; 1.0486x over previous
#include <cuda_runtime.h>
#include <cuda_bf16.h>
#include <cstdint>

#define NB 512      // batch
#define NT 256      // time steps
#define NF 128      // features
#define NH 1024     // hidden
#define NZ 4096     // 4*H
#define KTOT 1152   // NF + NH
#define FEATP 2064  // padded feature length
#define FEATR 2050  // real feature length

// ------------------ device scratch (no allocation allowed) ------------------
// Fragment-layout arrays, hi/lo interleaved per 1KB block: [hi 512B][lo 512B].
__device__ __align__(16) __nv_bfloat16 g_Wf[(size_t)NZ * KTOT * 2];      // W^T frag blocks [J][72]
__device__ __align__(16) __nv_bfloat16 g_xf[(size_t)NB * NT * NF * 2];   // x frag blocks [mb][NT][8]
__device__ __align__(16) __nv_bfloat16 g_hf2[2 * (size_t)NB * NH * 2];   // h frag blocks [buf][mb][64]
__device__ float g_c[NB * NH];
__device__ float g_hf[NB * NH];
__device__ float g_feat[NB * FEATP];
__device__ float g_vlp[NB * 512];
__device__ float g_qlp[NB * 512];
__device__ float g_vle[NB * 512];
__device__ float g_qle[NB * 512];
__device__ float g_sq[NB];

// ------------------ helpers ------------------
#define MMA16816(d, a, b) \
    asm volatile("mma.sync.aligned.m16n8k16.row.col.f32.bf16.bf16.f32 " \
                 "{%0,%1,%2,%3}, {%4,%5,%6,%7}, {%8,%9}, {%0,%1,%2,%3};" \
                 : "+f"((d)[0]), "+f"((d)[1]), "+f"((d)[2]), "+f"((d)[3]) \
                 : "r"((a)[0]), "r"((a)[1]), "r"((a)[2]), "r"((a)[3]), \
                   "r"((b)[0]), "r"((b)[1]))

__device__ __forceinline__ float fsig(float x)
{
    float e = __expf(-x);
    return __fdividef(1.f, 1.f + e);
}
__device__ __forceinline__ float ftanh(float x)
{
    float e = __expf(2.f * x);
    return 1.f - __fdividef(2.f, e + 1.f);
}

// ------------------ prep kernels ------------------
__global__ void k_init()
{
    int i = blockIdx.x * blockDim.x + threadIdx.x;
    if (i < NB * NH) g_c[i] = 0.f;
    if (i < NB * NH * 2) g_hf2[i] = __float2bfloat16(0.f);   // h buffer 0
}

// W -> permuted (col j = u*4+gate), split hi/lo, B-fragment layout, hi/lo interleaved blocks.
__global__ void k_prep_w(const float* __restrict__ W)
{
    int id = blockIdx.x * blockDim.x + threadIdx.x;
    if (id >= NZ * KTOT) return;
    int j = id / KTOT;
    int k = id - j * KTOT;
    int u = j >> 2;
    int g = j & 3;
    float w = W[(size_t)k * NZ + g * NH + u];
    __nv_bfloat16 hi = __float2bfloat16(w);
    float lo = w - __bfloat162float(hi);
    int J = j >> 4;
    int n16 = j & 15;
    int K16 = k >> 4;
    int kk = k & 15;
    int lane = (n16 & 7) * 4 + ((kk & 7) >> 1);
    int reg = (n16 >> 3) * 2 + (kk >> 3);
    int half = kk & 1;
    size_t out = ((size_t)J * 72 + K16) * 512 + lane * 8 + reg * 2 + half;
    g_Wf[out] = hi;
    g_Wf[out + 256] = __float2bfloat16(lo);
}

// history -> split hi/lo, A-fragment layout, hi/lo interleaved blocks [mb][t][kb].
__global__ void k_prep_x(const float* __restrict__ hist)
{
    int id = blockIdx.x * blockDim.x + threadIdx.x;
    if (id >= NB * NT * NF) return;
    int b = id / (NT * NF);
    int r = id - b * (NT * NF);
    int t = r / NF;
    int f = r - t * NF;
    float v = hist[id];
    __nv_bfloat16 hi = __float2bfloat16(v);
    float lo = v - __bfloat162float(hi);
    int mb = b >> 4, row = b & 15;
    int kb = f >> 4, kk = f & 15;
    int lane = (row & 7) * 4 + ((kk & 7) >> 1);
    int reg = (row >> 3) + 2 * (kk >> 3);
    int half = kk & 1;
    size_t out = ((size_t)(mb * NT + t) * 8 + kb) * 512 + lane * 8 + reg * 2 + half;
    g_xf[out] = hi;
    g_xf[out + 256] = __float2bfloat16(lo);
}

// ------------------ fused LSTM step: smem-free fragment-direct GEMM + cell ------------------
// grid (64 n-tiles, 4 m-tiles), 256 threads (8 warps, 4m x 2n, warp 32m x 32n).
// No smem, no barriers. Asymmetric register prefetch: A depth-2, B depth-3 (W has the
// long-latency path). K loop unrolled by 6 so buffer indices are static.
__global__ __launch_bounds__(256, 2) void k_step(const float* __restrict__ blstm, int t)
{
    const int tid = threadIdx.x;
    const int wid = tid >> 5;
    const int lane = tid & 31;
    const int ntile = blockIdx.x;
    const int mtile = blockIdx.y;
    const int wm = wid & 3;
    const int wn = wid >> 2;
    const int u0 = ntile * 16;
    const int m0 = mtile * 128;

    const size_t HB = (size_t)NB * NH * 2;
    const size_t hrd = (size_t)(t & 1) * HB;
    const size_t hwr = (size_t)((t + 1) & 1) * HB;

    float acc[2][4][4];
#pragma unroll
    for (int a = 0; a < 2; ++a)
#pragma unroll
        for (int b = 0; b < 4; ++b)
#pragma unroll
            for (int cc = 0; cc < 4; ++cc) acc[a][b][cc] = 0.f;

    const int mbG0 = mtile * 8 + wm * 2;
    const int J0 = ntile * 4 + wn * 2;

    const __nv_bfloat16* pX = g_xf + ((size_t)(mbG0 * NT + t) * 8) * 512 + lane * 8;
    const __nv_bfloat16* pH = g_hf2 + hrd + ((size_t)mbG0 * 64) * 512 + lane * 8;
    const __nv_bfloat16* pB = g_Wf + ((size_t)J0 * 72) * 512 + lane * 8;

    const size_t XMT = (size_t)NT * 8 * 512;   // x mt stride (elems)
    const size_t HMT = (size_t)64 * 512;       // h mt stride
    const size_t BNP = (size_t)72 * 512;       // B np stride

    uint4 Ah[2][2], Al[2][2];   // [buf][mt]
    uint4 Bh[3][2], Bl[3][2];   // [buf][np]

    auto ldA = [&](int s, int buf) {
        const __nv_bfloat16* base;
        size_t mts;
        if (s < 8) { base = pX + (size_t)s * 512; mts = XMT; }
        else       { base = pH + (size_t)(s - 8) * 512; mts = HMT; }
        Ah[buf][0] = *(const uint4*)(base);
        Al[buf][0] = *(const uint4*)(base + 256);
        Ah[buf][1] = *(const uint4*)(base + mts);
        Al[buf][1] = *(const uint4*)(base + mts + 256);
    };
    auto ldB = [&](int s, int buf) {
        const __nv_bfloat16* base = pB + (size_t)s * 512;
        Bh[buf][0] = *(const uint4*)(base);
        Bl[buf][0] = *(const uint4*)(base + 256);
        Bh[buf][1] = *(const uint4*)(base + BNP);
        Bl[buf][1] = *(const uint4*)(base + BNP + 256);
    };

    auto domma = [&](int ia, int ib) {
        // term-major: hh, hl, lh (identical accumulation order to round 9)
#pragma unroll
        for (int mt = 0; mt < 2; ++mt)
#pragma unroll
            for (int nt = 0; nt < 4; ++nt)
                MMA16816(acc[mt][nt], ((uint32_t*)&Ah[ia][mt]),
                         ((uint32_t*)&Bh[ib][nt >> 1]) + (nt & 1) * 2);
#pragma unroll
        for (int mt = 0; mt < 2; ++mt)
#pragma unroll
            for (int nt = 0; nt < 4; ++nt)
                MMA16816(acc[mt][nt], ((uint32_t*)&Ah[ia][mt]),
                         ((uint32_t*)&Bl[ib][nt >> 1]) + (nt & 1) * 2);
#pragma unroll
        for (int mt = 0; mt < 2; ++mt)
#pragma unroll
            for (int nt = 0; nt < 4; ++nt)
                MMA16816(acc[mt][nt], ((uint32_t*)&Al[ia][mt]),
                         ((uint32_t*)&Bh[ib][nt >> 1]) + (nt & 1) * 2);
    };

    ldA(0, 0);
    ldB(0, 0);
    ldA(1, 1);
    ldB(1, 1);
    ldB(2, 2);

#pragma unroll 1
    for (int s = 0; s < 72; s += 6) {
#pragma unroll
        for (int i = 0; i < 6; ++i) {
            const int q = s + i;
            domma(i & 1, i % 3);
            if (q + 2 < 72) ldA(q + 2, i & 1);
            if (q + 3 < 72) ldB(q + 3, i % 3);
        }
    }

    // ---- fused cell epilogue (register accumulators) ----
    const int g = lane >> 2;
    const int tq = lane & 3;
    const bool even = (tq & 1) == 0;
#pragma unroll
    for (int mt = 0; mt < 2; ++mt) {
#pragma unroll
        for (int nt = 0; nt < 4; ++nt) {
            float c0 = acc[mt][nt][0], c1 = acc[mt][nt][1];
            float c2 = acc[mt][nt][2], c3 = acc[mt][nt][3];
            float s0 = even ? c2 : c0;
            float s1 = even ? c3 : c1;
            float r0 = __shfl_xor_sync(0xffffffffu, s0, 1);
            float r1 = __shfl_xor_sync(0xffffffffu, s1, 1);
            float zi, zj, zf, zo;
            int row;
            if (even) { row = g;     zi = c0; zj = c1; zf = r0; zo = r1; }
            else      { row = g + 8; zi = r0; zj = r1; zf = c2; zo = c3; }
            int u = u0 + wn * 8 + nt * 2 + (tq >> 1);
            int m = m0 + wm * 32 + mt * 16 + row;
            float bi = blstm[u];
            float bj = blstm[NH + u];
            float bf_ = blstm[2 * NH + u];
            float bo = blstm[3 * NH + u];
            size_t idx = (size_t)m * NH + u;
            float cold = g_c[idx];
            float cn = fsig(zf + bf_ + 1.f) * cold + fsig(zi + bi) * ftanh(zj + bj);
            float h = fsig(zo + bo) * ftanh(cn);
            g_c[idx] = cn;
            g_hf[idx] = h;
            __nv_bfloat16 hb = __float2bfloat16(h);
            __nv_bfloat16 lb = __float2bfloat16(h - __bfloat162float(hb));
            int mb = m >> 4, rowb = m & 15, kb = u >> 4, kk = u & 15;
            int lane2 = (rowb & 7) * 4 + ((kk & 7) >> 1);
            int reg = (rowb >> 3) + 2 * (kk >> 3);
            int half = kk & 1;
            size_t fo = ((size_t)(mb * 64 + kb)) * 512 + lane2 * 8 + reg * 2 + half;
            g_hf2[hwr + fo] = hb;
            g_hf2[hwr + fo + 256] = lb;
        }
    }
}

// ------------------ feature assembly + head MLPs ------------------
__global__ void k_feat(const float* __restrict__ head)
{
    int idx = blockIdx.x * blockDim.x + threadIdx.x;
    if (idx >= NB * FEATP) return;
    int b = idx / FEATP;
    int k = idx - b * FEATP;
    float v;
    if (k < 2)            v = head[b * 3 + 1 + k];
    else if (k < 1026)    v = g_c[b * NH + (k - 2)];
    else if (k < 2050)    v = g_hf[b * NH + (k - 1026)];
    else                  v = 0.f;
    g_feat[idx] = v;
}

__global__ __launch_bounds__(256) void k_head_gemm(
    const float* __restrict__ W3, const float* __restrict__ b3,
    const float* __restrict__ W4, const float* __restrict__ b4,
    const float* __restrict__ W5, const float* __restrict__ b5,
    const float* __restrict__ W6, const float* __restrict__ b6)
{
    const int which = blockIdx.z;
    const float* Wm = (which == 0) ? W3 : (which == 1) ? W4 : (which == 2) ? W5 : W6;
    const float* bv = (which == 0) ? b3 : (which == 1) ? b4 : (which == 2) ? b5 : b6;
    float* Cout = (which == 0) ? g_vlp : (which == 1) ? g_qlp : (which == 2) ? g_vle : g_qle;

    __shared__ float As[16][64];
    __shared__ float Bs[16][64];
    const int tid = threadIdx.x;
    const int tx = tid & 15;
    const int ty = tid >> 4;
    const int m0 = blockIdx.y * 64;
    const int n0 = blockIdx.x * 64;

    float acc[4][4];
#pragma unroll
    for (int i = 0; i < 4; ++i)
#pragma unroll
        for (int j = 0; j < 4; ++j) acc[i][j] = 0.f;

    const int KT = FEATP / 16;
    for (int kt = 0; kt < KT; ++kt) {
        const int kbase = kt * 16;
        {
            int idx = tid;
            int m  = idx >> 2;
            int k4 = (idx & 3) * 4;
            float4 v = *(const float4*)(g_feat + (size_t)(m0 + m) * FEATP + kbase + k4);
            As[k4 + 0][m] = v.x;
            As[k4 + 1][m] = v.y;
            As[k4 + 2][m] = v.z;
            As[k4 + 3][m] = v.w;
            int kb = idx >> 4;
            int nb = (idx & 15) * 4;
            int kg = kbase + kb;
            float4 w = make_float4(0.f, 0.f, 0.f, 0.f);
            if (kg < FEATR)
                w = *(const float4*)(Wm + (size_t)kg * 512 + n0 + nb);
            *(float4*)&Bs[kb][nb] = w;
        }
        __syncthreads();
#pragma unroll
        for (int kk = 0; kk < 16; ++kk) {
            float a[4], b[4];
            *(float4*)&a[0] = *(const float4*)&As[kk][ty * 4];
            *(float4*)&b[0] = *(const float4*)&Bs[kk][tx * 4];
#pragma unroll
            for (int i = 0; i < 4; ++i)
#pragma unroll
                for (int j = 0; j < 4; ++j)
                    acc[i][j] += a[i] * b[j];
        }
        __syncthreads();
    }

#pragma unroll
    for (int i = 0; i < 4; ++i) {
        int m = m0 + ty * 4 + i;
        int n = n0 + tx * 4;
        float4 r;
        r.x = acc[i][0] + bv[n + 0];
        r.y = acc[i][1] + bv[n + 1];
        r.z = acc[i][2] + bv[n + 2];
        r.w = acc[i][3] + bv[n + 3];
        r.x = r.x > 0.f ? r.x : 0.f;
        r.y = r.y > 0.f ? r.y : 0.f;
        r.z = r.z > 0.f ? r.z : 0.f;
        r.w = r.w > 0.f ? r.w : 0.f;
        *(float4*)(Cout + (size_t)m * 512 + n) = r;
    }
}

__global__ void k_combine(
    const float* __restrict__ head, const float* __restrict__ targetQ,
    const int* __restrict__ action,
    const float* __restrict__ Wsv, const float* __restrict__ bsv,
    const float* __restrict__ Wbv, const float* __restrict__ bbv,
    const float* __restrict__ Wsh, const float* __restrict__ bsh,
    const float* __restrict__ Wbh, const float* __restrict__ bbh,
    float* __restrict__ out, int out_size)
{
    const int b = blockIdx.x;
    const int tid = threadIdx.x;
    float s0 = 0.f, s1 = 0.f, s2 = 0.f, s3 = 0.f, s4 = 0.f, s5 = 0.f;
    for (int k = tid; k < 512; k += 128) {
        float vp = g_vlp[b * 512 + k];
        float qp = g_qlp[b * 512 + k];
        float ve = g_vle[b * 512 + k];
        float qe = g_qle[b * 512 + k];
        s0 += vp * Wsv[k];
        s1 += qp * Wsh[2 * k];
        s2 += qp * Wsh[2 * k + 1];
        s3 += ve * Wbv[k];
        s4 += qe * Wbh[2 * k];
        s5 += qe * Wbh[2 * k + 1];
    }
    __shared__ float red[6][128];
    red[0][tid] = s0; red[1][tid] = s1; red[2][tid] = s2;
    red[3][tid] = s3; red[4][tid] = s4; red[5][tid] = s5;
    __syncthreads();
    for (int off = 64; off > 0; off >>= 1) {
        if (tid < off) {
#pragma unroll
            for (int i = 0; i < 6; ++i) red[i][tid] += red[i][tid + off];
        }
        __syncthreads();
    }
    if (tid == 0) {
        float sellv = red[0][0] + bsv[0];
        float pa0 = red[1][0] + bsh[0];
        float pa1 = red[2][0] + bsh[1];
        float buyv = red[3][0] + bbv[0];
        float ea0 = red[4][0] + bbh[0];
        float ea1 = red[5][0] + bbh[1];
        float pm = 0.5f * (pa0 + pa1);
        float em = 0.5f * (ea0 + ea1);
        float pQ0 = pa0 - pm + sellv;
        float pQ1 = pa1 - pm + sellv;
        float eQ0 = ea0 - em + buyv;
        float eQ1 = ea1 - em + buyv;
        float isp = head[b * 3];
        float Q0, Q1;
        if (isp != 0.f) { Q0 = pQ0; Q1 = eQ1; }
        else            { Q0 = eQ0; Q1 = pQ1; }
        if (out_size >= 1 + 2 * NB) {
            out[1 + 2 * b]     = Q0;
            out[1 + 2 * b + 1] = Q1;
        }
        if (out_size >= 1 + 2 * NB + NB) {
            out[1 + 2 * NB + b] = (Q1 > Q0) ? 1.f : 0.f;
        }
        int a = action[b];
        float iv = (a == 0) ? Q0 : Q1;
        float d = targetQ[b] - iv;
        g_sq[b] = d * d;
    }
}

__global__ void k_loss(float* __restrict__ out, int out_size)
{
    __shared__ float r[256];
    int tid = threadIdx.x;
    r[tid] = g_sq[tid] + g_sq[tid + 256];
    __syncthreads();
    for (int off = 128; off > 0; off >>= 1) {
        if (tid < off) r[tid] += r[tid + off];
        __syncthreads();
    }
    if (tid == 0 && out_size >= 1) out[0] = r[0] * (1.f / 512.f);
}

// ------------------ launch ------------------
extern "C" void kernel_launch(void* const* d_in, const int* in_sizes, int n_in,
                              void* d_out, int out_size)
{
    const float* hist    = (const float*)d_in[0];
    const float* head    = (const float*)d_in[1];
    const float* targetQ = (const float*)d_in[2];
    const int*   action  = (const int*)d_in[3];
    const float* W_lstm  = (const float*)d_in[4];
    const float* b_lstm  = (const float*)d_in[5];
    const float* W3 = (const float*)d_in[6],  *b3 = (const float*)d_in[7];
    const float* W4 = (const float*)d_in[8],  *b4 = (const float*)d_in[9];
    const float* W5 = (const float*)d_in[10], *b5 = (const float*)d_in[11];
    const float* W6 = (const float*)d_in[12], *b6 = (const float*)d_in[13];
    const float* Wsv = (const float*)d_in[14], *bsv = (const float*)d_in[15];
    const float* Wbv = (const float*)d_in[16], *bbv = (const float*)d_in[17];
    const float* Wsh = (const float*)d_in[18], *bsh = (const float*)d_in[19];
    const float* Wbh = (const float*)d_in[20], *bbh = (const float*)d_in[21];
    float* out = (float*)d_out;

    k_init<<<(NB * NH * 2 + 255) / 256, 256>>>();
    k_prep_w<<<((size_t)NZ * KTOT + 255) / 256, 256>>>(W_lstm);
    k_prep_x<<<((size_t)NB * NT * NF + 255) / 256, 256>>>(hist);

    dim3 gl(64, 4);  // 256 CTAs, no smem, no barriers
    for (int t = 0; t < NT; ++t)
        k_step<<<gl, 256>>>(b_lstm, t);

    k_feat<<<(NB * FEATP + 255) / 256, 256>>>(head);

    dim3 gh(8, 8, 4);
    k_head_gemm<<<gh, 256>>>(W3, b3, W4, b4, W5, b5, W6, b6);

    k_combine<<<NB, 128>>>(head, targetQ, action,
                           Wsv, bsv, Wbv, bbv, Wsh, bsh, Wbh, bbh,
                           out, out_size);
    k_loss<<<1, 256>>>(out, out_size);
}